// round 8
// baseline (speedup 1.0000x reference)
#include <cuda_runtime.h>
#include <cuda_fp16.h>
#include <math.h>
#include <stdint.h>

#define SQ   2048
#define DM   2048
#define DH   128
#define NH   16
#define DL   512
#define BB   4
#define MTOT (BB*SQ)

// ---------------- scratch ------------------------------------------------------
__device__ __half g_xhi[(size_t)MTOT * DM],  g_xlo[(size_t)MTOT * DM];
__device__ __half g_lathi[(size_t)MTOT * DL], g_latlo[(size_t)MTOT * DL];
__device__ __half g_khi[(size_t)MTOT * DM],  g_klo[(size_t)MTOT * DM];
__device__ __half g_qhi[(size_t)MTOT * DM],  g_qlo[(size_t)MTOT * DM];
__device__ __half g_ctxhi[(size_t)MTOT * DM], g_ctxlo[(size_t)MTOT * DM];
__device__ __half g_vthi[(size_t)BB * NH * DH * SQ], g_vtlo[(size_t)BB * NH * DH * SQ];
__device__ __half g_wdh[(size_t)DM * DL], g_wdl[(size_t)DM * DL];
__device__ __half g_wukh[(size_t)DL * DM], g_wukl[(size_t)DL * DM];
__device__ __half g_wuvh[(size_t)DL * DM], g_wuvl[(size_t)DL * DM];
__device__ __half g_wqh[(size_t)DM * DM],  g_wql[(size_t)DM * DM];
__device__ __half g_woh[(size_t)DM * DM],  g_wol[(size_t)DM * DM];

// ---------------- helpers ------------------------------------------------------
__device__ __forceinline__ uint32_t smem_u32(const void* p) {
    uint32_t a;
    asm("{ .reg .u64 t; cvta.to.shared.u64 t, %1; cvt.u32.u64 %0, t; }" : "=r"(a) : "l"(p));
    return a;
}
__device__ __forceinline__ void cp_async16(uint32_t dst, const void* src) {
    asm volatile("cp.async.cg.shared.global [%0], [%1], 16;" :: "r"(dst), "l"(src) : "memory");
}
#define CP_COMMIT() asm volatile("cp.async.commit_group;" ::: "memory")
#define CP_WAIT1()  asm volatile("cp.async.wait_group 1;" ::: "memory")

__device__ __forceinline__ void split_h2(float2 f, uint32_t& hi, uint32_t& lo) {
    __half2 h = __float22half2_rn(f);
    float2 back = __half22float2(h);
    __half2 l = __float22half2_rn(make_float2(f.x - back.x, f.y - back.y));
    hi = *(uint32_t*)&h;
    lo = *(uint32_t*)&l;
}
__device__ __forceinline__ uint32_t pack_h2(float a, float b) {
    __half2 h = __float22half2_rn(make_float2(a, b));
    return *(uint32_t*)&h;
}
__device__ __forceinline__ void mma_f16(float* c, const uint32_t* a, const uint32_t* b) {
    asm volatile(
        "mma.sync.aligned.m16n8k16.row.col.f32.f16.f16.f32 "
        "{%0,%1,%2,%3}, {%4,%5,%6,%7}, {%8,%9}, {%0,%1,%2,%3};"
        : "+f"(c[0]), "+f"(c[1]), "+f"(c[2]), "+f"(c[3])
        : "r"(a[0]), "r"(a[1]), "r"(a[2]), "r"(a[3]), "r"(b[0]), "r"(b[1]));
}
__device__ __forceinline__ int inv_pair(int p) { return ((p & 3) << 1) | (p >> 2); }

// ---------------- prep: x split + 5 weight transpose/splits (z-indexed) --------
__global__ void prep_kernel(const float* __restrict__ x,
                            const float* __restrict__ Wd, const float* __restrict__ Wuk,
                            const float* __restrict__ Wuv, const float* __restrict__ Wq,
                            const float* __restrict__ Wo)
{
    const int z = blockIdx.z;
    if (z == 0) {
        // split x rows -> fp16 hi/lo (pair-permuted along DM)
        const int tid = threadIdx.y * 32 + threadIdx.x;
        long long base = ((long long)blockIdx.y * 64 + blockIdx.x) * 256 + tid;
        const long long tot = (long long)MTOT * DM / 2;
        for (long long i2 = base; i2 < tot; i2 += (long long)4096 * 256) {
            int d2 = (int)(i2 & (DM / 2 - 1));
            long long row = i2 >> 10;
            int d2p = (d2 & ~7) | inv_pair(d2 & 7);
            float2 v = ((const float2*)x)[i2];
            uint32_t h, l;
            split_h2(v, h, l);
            ((uint32_t*)g_xhi)[row * (DM / 2) + d2p] = h;
            ((uint32_t*)g_xlo)[row * (DM / 2) + d2p] = l;
        }
        return;
    }
    // weight transpose+split: W[R][Cc] -> Wt hi/lo [Cc][R], R pair-permuted
    const float* in; __half *hi, *lo; int Cc, R;
    if      (z == 1) { in = Wd;  hi = g_wdh;  lo = g_wdl;  Cc = DL; R = DM; }
    else if (z == 2) { in = Wuk; hi = g_wukh; lo = g_wukl; Cc = DM; R = DL; }
    else if (z == 3) { in = Wuv; hi = g_wuvh; lo = g_wuvl; Cc = DM; R = DL; }
    else if (z == 4) { in = Wq;  hi = g_wqh;  lo = g_wql;  Cc = DM; R = DM; }
    else             { in = Wo;  hi = g_woh;  lo = g_wol;  Cc = DM; R = DM; }
    const int c0 = blockIdx.x * 32, r0 = blockIdx.y * 32;
    if (c0 >= Cc || r0 >= R) return;

    __shared__ float t[32][33];
#pragma unroll
    for (int i = threadIdx.y; i < 32; i += 8)
        t[i][threadIdx.x] = in[(long long)(r0 + i) * Cc + c0 + threadIdx.x];
    __syncthreads();
    const int e = r0 + threadIdx.x;
    const int p = e >> 1, bo = e & 1;
    const int pe = (((p & ~7) | inv_pair(p & 7)) << 1) | bo;
#pragma unroll
    for (int i = threadIdx.y; i < 32; i += 8) {
        float v = t[threadIdx.x][i];
        __half h = __float2half_rn(v);
        __half l = __float2half_rn(v - __half2float(h));
        hi[(long long)(c0 + i) * R + pe] = h;
        lo[(long long)(c0 + i) * R + pe] = l;
    }
}

// ---------------- pre-split fp16 hi/lo GEMM ------------------------------------
// D = (A @ B^T + bias) * post; outputs: fp32 Cf, or split Chi/Clo, or V^T split.
#define BK 32
#define AROW 80
#define ARR (128 * AROW)
#define HSTAGE (4 * ARR)
#define SMEM_HGEMM (2 * HSTAGE)         // 81920

__global__ __launch_bounds__(256, 2)
void hgemm(const __half* __restrict__ Ah, const __half* __restrict__ Al,
           const __half* __restrict__ Bh, const __half* __restrict__ Bl,
           float* __restrict__ Cf, __half* __restrict__ Chi, __half* __restrict__ Clo,
           __half* __restrict__ VtHi, __half* __restrict__ VtLo,
           const float* __restrict__ bias,
           int K, int lda, int ldb, int ldc, float post)
{
    extern __shared__ char sm[];
    const uint32_t smb = smem_u32(sm);
    const int tid = threadIdx.x, wid = tid >> 5, lane = tid & 31;
    const int qr = lane >> 2, qc = lane & 3;
    const int warpM = (wid & 1) * 64, warpN = (wid >> 1) * 32;
    const int m0 = blockIdx.y * 128, n0 = blockIdx.x * 128;

    const __half* A0 = Ah + (long long)m0 * lda;
    const __half* A1 = Al + (long long)m0 * lda;
    const __half* B0 = Bh + (long long)n0 * ldb;
    const __half* B1 = Bl + (long long)n0 * ldb;

    float acc[4][4][4];
#pragma unroll
    for (int mi = 0; mi < 4; mi++)
#pragma unroll
        for (int ni = 0; ni < 4; ni++)
#pragma unroll
            for (int t = 0; t < 4; t++) acc[mi][ni][t] = 0.0f;

    auto load_stage = [&](int t, int s) {
        const int k0 = t * BK;
        uint32_t base = smb + s * HSTAGE;
#pragma unroll
        for (int j = 0; j < 2; j++) {
            int g = tid + j * 256;
            int r = g >> 2, c = g & 3;
            uint32_t off = (uint32_t)(r * AROW + c * 16);
            cp_async16(base + off,           A0 + (long long)r * lda + k0 + c * 8);
            cp_async16(base + ARR + off,     A1 + (long long)r * lda + k0 + c * 8);
            cp_async16(base + 2 * ARR + off, B0 + (long long)r * ldb + k0 + c * 8);
            cp_async16(base + 3 * ARR + off, B1 + (long long)r * ldb + k0 + c * 8);
        }
    };

    const int nk = K / BK;
    load_stage(0, 0); CP_COMMIT();
    load_stage(1, 1); CP_COMMIT();

    for (int i = 0; i < nk; i++) {
        CP_WAIT1();
        __syncthreads();
        const char* s = sm + (i & 1) * HSTAGE;
#pragma unroll
        for (int kk = 0; kk < 2; kk++) {
            uint32_t aH[4][4], aL[4][4], bH[4][2], bL[4][2];
#pragma unroll
            for (int mi = 0; mi < 4; mi++) {
                int row = warpM + mi * 16 + qr;
                uint2 v0 = *(const uint2*)(s + row * AROW + kk * 32 + qc * 8);
                uint2 v1 = *(const uint2*)(s + (row + 8) * AROW + kk * 32 + qc * 8);
                aH[mi][0] = v0.x; aH[mi][2] = v0.y; aH[mi][1] = v1.x; aH[mi][3] = v1.y;
                uint2 w0 = *(const uint2*)(s + ARR + row * AROW + kk * 32 + qc * 8);
                uint2 w1 = *(const uint2*)(s + ARR + (row + 8) * AROW + kk * 32 + qc * 8);
                aL[mi][0] = w0.x; aL[mi][2] = w0.y; aL[mi][1] = w1.x; aL[mi][3] = w1.y;
            }
#pragma unroll
            for (int ni = 0; ni < 4; ni++) {
                int col = warpN + ni * 8 + qr;
                uint2 v = *(const uint2*)(s + 2 * ARR + col * AROW + kk * 32 + qc * 8);
                bH[ni][0] = v.x; bH[ni][1] = v.y;
                uint2 w = *(const uint2*)(s + 3 * ARR + col * AROW + kk * 32 + qc * 8);
                bL[ni][0] = w.x; bL[ni][1] = w.y;
            }
#pragma unroll
            for (int mi = 0; mi < 4; mi++)
#pragma unroll
                for (int ni = 0; ni < 4; ni++) {
                    mma_f16(acc[mi][ni], aL[mi], bH[ni]);
                    mma_f16(acc[mi][ni], aH[mi], bL[ni]);
                    mma_f16(acc[mi][ni], aH[mi], bH[ni]);
                }
        }
        __syncthreads();
        if (i + 2 < nk) load_stage(i + 2, i & 1);
        CP_COMMIT();
    }

    if (VtHi) {
        // V^T split epilogue: stage fp32 tile, write transposed hi/lo (s permuted)
        __syncthreads();
        float* tile = (float*)sm;   // [128][132]
#pragma unroll
        for (int mi = 0; mi < 4; mi++)
#pragma unroll
            for (int ni = 0; ni < 4; ni++) {
                int rl = warpM + mi * 16 + qr;
                int cl = warpN + ni * 8 + qc * 2;
                float2 bv = *(const float2*)(bias + n0 + cl);
                tile[rl * 132 + cl]       = acc[mi][ni][0] + bv.x;
                tile[rl * 132 + cl + 1]   = acc[mi][ni][1] + bv.y;
                tile[(rl + 8) * 132 + cl]     = acc[mi][ni][2] + bv.x;
                tile[(rl + 8) * 132 + cl + 1] = acc[mi][ni][3] + bv.y;
            }
        __syncthreads();
        const int h = n0 >> 7;           // head
        const int bb = m0 >> 11;         // batch
        const int s0g = m0 & (SQ - 1);
        const int dl = tid >> 1, sh = (tid & 1) * 64;
        long long base = ((long long)(bb * NH + h) * DH + dl) * SQ + s0g + sh;
#pragma unroll
        for (int pp = 0; pp < 32; pp++) {
            int e = 2 * pp;                       // local s within 64
            int g = e >> 4, q = pp & 7;
            int off = g * 16 + inv_pair(q) * 2;
            float v0 = tile[(sh + e) * 132 + dl];
            float v1 = tile[(sh + e + 1) * 132 + dl];
            uint32_t hh, ll;
            split_h2(make_float2(v0, v1), hh, ll);
            *(uint32_t*)(VtHi + base + off) = hh;
            *(uint32_t*)(VtLo + base + off) = ll;
        }
        return;
    }

    // normal epilogue
#pragma unroll
    for (int mi = 0; mi < 4; mi++) {
#pragma unroll
        for (int ni = 0; ni < 4; ni++) {
            int row = m0 + warpM + mi * 16 + qr;
            int colb = n0 + warpN + ni * 8;
            float2 bv = make_float2(0.f, 0.f);
            if (bias) bv = *(const float2*)(bias + colb + qc * 2);
            float2 v0 = make_float2((acc[mi][ni][0] + bv.x) * post, (acc[mi][ni][1] + bv.y) * post);
            float2 v1 = make_float2((acc[mi][ni][2] + bv.x) * post, (acc[mi][ni][3] + bv.y) * post);
            if (Cf) {
                *(float2*)(Cf + (long long)row * ldc + colb + qc * 2) = v0;
                *(float2*)(Cf + (long long)(row + 8) * ldc + colb + qc * 2) = v1;
            }
            if (Chi) {
                int p = (colb >> 1) + qc;
                int pp = (p & ~7) | inv_pair(p & 7);
                uint32_t h, l;
                split_h2(v0, h, l);
                ((uint32_t*)Chi)[(long long)row * (ldc >> 1) + pp] = h;
                ((uint32_t*)Clo)[(long long)row * (ldc >> 1) + pp] = l;
                split_h2(v1, h, l);
                ((uint32_t*)Chi)[(long long)(row + 8) * (ldc >> 1) + pp] = h;
                ((uint32_t*)Clo)[(long long)(row + 8) * (ldc >> 1) + pp] = l;
            }
        }
    }
}

// ---------------- fused flash attention (double-buffered K+V) ------------------
#define CHUNK 64
#define KROWB 272
#define VROWB 144
#define FSTG  71680
#define FKH(s) ((s) * FSTG + 0)
#define FKL(s) ((s) * FSTG + 17408)
#define FVH(s) ((s) * FSTG + 34816)
#define FVL(s) ((s) * FSTG + 53248)
#define SMEM_FLASH (2 * FSTG)            // 143360

__global__ __launch_bounds__(256)
void flash_kernel(const __half* __restrict__ Qhi, const __half* __restrict__ Qlo,
                  const __half* __restrict__ Khi, const __half* __restrict__ Klo,
                  const __half* __restrict__ Vhi, const __half* __restrict__ Vlo,
                  __half* __restrict__ Chi, __half* __restrict__ Clo)
{
    extern __shared__ char smc[];
    const uint32_t smb = smem_u32(smc);
    const int tid = threadIdx.x, wid = tid >> 5, lane = tid & 31;
    const int qr = lane >> 2, qc = lane & 3;
    const int bh = blockIdx.y, b = bh >> 4, h = bh & 15;
    const int q0 = blockIdx.x * 128;

    const long long rowA = (long long)(b * SQ + q0 + wid * 16 + qr);
    const long long qoff = rowA * DM + h * DH;
    uint32_t qh[8][4], ql[8][4];
#pragma unroll
    for (int kk = 0; kk < 8; kk++) {
        uint2 v0 = *(const uint2*)(Qhi + qoff + kk * 16 + qc * 4);
        uint2 v1 = *(const uint2*)(Qhi + qoff + 8 * DM + kk * 16 + qc * 4);
        qh[kk][0] = v0.x; qh[kk][2] = v0.y; qh[kk][1] = v1.x; qh[kk][3] = v1.y;
        uint2 w0 = *(const uint2*)(Qlo + qoff + kk * 16 + qc * 4);
        uint2 w1 = *(const uint2*)(Qlo + qoff + 8 * DM + kk * 16 + qc * 4);
        ql[kk][0] = w0.x; ql[kk][2] = w0.y; ql[kk][1] = w1.x; ql[kk][3] = w1.y;
    }

    float accO[16][4];
#pragma unroll
    for (int t = 0; t < 16; t++)
#pragma unroll
        for (int c = 0; c < 4; c++) accO[t][c] = 0.0f;
    float mr0 = -INFINITY, mr1 = -INFINITY, lr0 = 0.0f, lr1 = 0.0f;

    const __half* kh_g = Khi + (long long)(b * SQ) * DM + h * DH;
    const __half* kl_g = Klo + (long long)(b * SQ) * DM + h * DH;
    const __half* vh_g = Vhi + (long long)bh * DH * SQ;
    const __half* vl_g = Vlo + (long long)bh * DH * SQ;

    auto loadKV = [&](int j, int s) {
        int s0 = j * CHUNK;
        for (int g = tid; g < 1024; g += 256) {
            int r = g >> 4, c = g & 15;
            cp_async16(smb + FKH(s) + r * KROWB + c * 16, kh_g + (long long)(s0 + r) * DM + c * 8);
            cp_async16(smb + FKL(s) + r * KROWB + c * 16, kl_g + (long long)(s0 + r) * DM + c * 8);
        }
        for (int g = tid; g < 1024; g += 256) {
            int r = g >> 3, c = g & 7;
            cp_async16(smb + FVH(s) + r * VROWB + c * 16, vh_g + (long long)r * SQ + s0 + c * 8);
            cp_async16(smb + FVL(s) + r * VROWB + c * 16, vl_g + (long long)r * SQ + s0 + c * 8);
        }
    };

    loadKV(0, 0);
    CP_COMMIT();

    const int NCH = SQ / CHUNK;
    for (int j = 0; j < NCH; j++) {
        if (j + 1 < NCH) loadKV(j + 1, (j + 1) & 1);
        CP_COMMIT();
        CP_WAIT1();
        __syncthreads();
        const int st = j & 1;

        // ---- S = Q @ K^T (3-term) ----
        float accS[8][4];
#pragma unroll
        for (int t = 0; t < 8; t++)
#pragma unroll
            for (int c = 0; c < 4; c++) accS[t][c] = 0.0f;
#pragma unroll
        for (int kk = 0; kk < 8; kk++) {
#pragma unroll
            for (int t = 0; t < 8; t++) {
                uint2 bhv = *(const uint2*)(smc + FKH(st) + (8 * t + qr) * KROWB + kk * 32 + qc * 8);
                uint2 blv = *(const uint2*)(smc + FKL(st) + (8 * t + qr) * KROWB + kk * 32 + qc * 8);
                uint32_t bH[2] = {bhv.x, bhv.y}, bL[2] = {blv.x, blv.y};
                mma_f16(accS[t], ql[kk], bH);
                mma_f16(accS[t], qh[kk], bL);
                mma_f16(accS[t], qh[kk], bH);
            }
        }

        // ---- online softmax (rescale only when max moves) ----
        float mx0 = -INFINITY, mx1 = -INFINITY;
#pragma unroll
        for (int t = 0; t < 8; t++) {
            mx0 = fmaxf(mx0, fmaxf(accS[t][0], accS[t][1]));
            mx1 = fmaxf(mx1, fmaxf(accS[t][2], accS[t][3]));
        }
        mx0 = fmaxf(mx0, __shfl_xor_sync(0xFFFFFFFFu, mx0, 1));
        mx0 = fmaxf(mx0, __shfl_xor_sync(0xFFFFFFFFu, mx0, 2));
        mx1 = fmaxf(mx1, __shfl_xor_sync(0xFFFFFFFFu, mx1, 1));
        mx1 = fmaxf(mx1, __shfl_xor_sync(0xFFFFFFFFu, mx1, 2));
        if (mx0 > mr0 || mx1 > mr1) {
            float mn0 = fmaxf(mr0, mx0), mn1 = fmaxf(mr1, mx1);
            float al0 = __expf(mr0 - mn0), al1 = __expf(mr1 - mn1);
            mr0 = mn0; mr1 = mn1;
            lr0 *= al0; lr1 *= al1;
#pragma unroll
            for (int t = 0; t < 16; t++) {
                accO[t][0] *= al0; accO[t][1] *= al0;
                accO[t][2] *= al1; accO[t][3] *= al1;
            }
        }
        uint32_t ph[8][2];
#pragma unroll
        for (int t = 0; t < 8; t++) {
            float p0 = __expf(accS[t][0] - mr0);
            float p1 = __expf(accS[t][1] - mr0);
            float p2 = __expf(accS[t][2] - mr1);
            float p3 = __expf(accS[t][3] - mr1);
            lr0 += p0 + p1;
            lr1 += p2 + p3;
            ph[t][0] = pack_h2(p0, p1);
            ph[t][1] = pack_h2(p2, p3);
        }

        // ---- O += P @ (Vh + Vl), P single fp16 ----
#pragma unroll
        for (int kk2 = 0; kk2 < 4; kk2++) {
            uint32_t aH[4] = {ph[2 * kk2][0], ph[2 * kk2][1], ph[2 * kk2 + 1][0], ph[2 * kk2 + 1][1]};
#pragma unroll
            for (int t = 0; t < 16; t++) {
                uint2 vh2 = *(const uint2*)(smc + FVH(st) + (8 * t + qr) * VROWB + kk2 * 32 + qc * 8);
                uint2 vl2 = *(const uint2*)(smc + FVL(st) + (8 * t + qr) * VROWB + kk2 * 32 + qc * 8);
                uint32_t bH[2] = {vh2.x, vh2.y}, bL[2] = {vl2.x, vl2.y};
                mma_f16(accO[t], aH, bL);
                mma_f16(accO[t], aH, bH);
            }
        }
        __syncthreads();
    }

    // ---- epilogue ----
    lr0 += __shfl_xor_sync(0xFFFFFFFFu, lr0, 1);
    lr0 += __shfl_xor_sync(0xFFFFFFFFu, lr0, 2);
    lr1 += __shfl_xor_sync(0xFFFFFFFFu, lr1, 1);
    lr1 += __shfl_xor_sync(0xFFFFFFFFu, lr1, 2);
    const float i0 = 1.0f / lr0, i1 = 1.0f / lr1;
#pragma unroll
    for (int t = 0; t < 16; t++) {
        int p = 64 * h + 4 * t + qc;
        int pp = (p & ~7) | inv_pair(p & 7);
        uint32_t hh, ll;
        split_h2(make_float2(accO[t][0] * i0, accO[t][1] * i0), hh, ll);
        ((uint32_t*)Chi)[rowA * (DM / 2) + pp] = hh;
        ((uint32_t*)Clo)[rowA * (DM / 2) + pp] = ll;
        split_h2(make_float2(accO[t][2] * i1, accO[t][3] * i1), hh, ll);
        ((uint32_t*)Chi)[(rowA + 8) * (DM / 2) + pp] = hh;
        ((uint32_t*)Clo)[(rowA + 8) * (DM / 2) + pp] = ll;
    }
}

// ---------------- launch -------------------------------------------------------
extern "C" void kernel_launch(void* const* d_in, const int* in_sizes, int n_in,
                              void* d_out, int out_size)
{
    const float* x      = (const float*)d_in[0];
    const float* W_down = (const float*)d_in[1];
    const float* b_down = (const float*)d_in[2];
    const float* W_uk   = (const float*)d_in[3];
    const float* b_uk   = (const float*)d_in[4];
    const float* W_uv   = (const float*)d_in[5];
    const float* b_uv   = (const float*)d_in[6];
    const float* W_q    = (const float*)d_in[7];
    const float* b_q    = (const float*)d_in[8];
    const float* W_o    = (const float*)d_in[9];
    const float* b_o    = (const float*)d_in[10];
    float* out = (float*)d_out;

    void *pa;
    cudaGetSymbolAddress(&pa, g_xhi);   __half* xhi = (__half*)pa;
    cudaGetSymbolAddress(&pa, g_xlo);   __half* xlo = (__half*)pa;
    cudaGetSymbolAddress(&pa, g_lathi); __half* lathi = (__half*)pa;
    cudaGetSymbolAddress(&pa, g_latlo); __half* latlo = (__half*)pa;
    cudaGetSymbolAddress(&pa, g_khi);   __half* khi = (__half*)pa;
    cudaGetSymbolAddress(&pa, g_klo);   __half* klo = (__half*)pa;
    cudaGetSymbolAddress(&pa, g_qhi);   __half* qhi = (__half*)pa;
    cudaGetSymbolAddress(&pa, g_qlo);   __half* qlo = (__half*)pa;
    cudaGetSymbolAddress(&pa, g_ctxhi); __half* ctxhi = (__half*)pa;
    cudaGetSymbolAddress(&pa, g_ctxlo); __half* ctxlo = (__half*)pa;
    cudaGetSymbolAddress(&pa, g_vthi);  __half* vthi = (__half*)pa;
    cudaGetSymbolAddress(&pa, g_vtlo);  __half* vtlo = (__half*)pa;
    __half *wdh, *wdl, *wukh, *wukl, *wuvh, *wuvl, *wqh, *wql, *woh, *wol;
    cudaGetSymbolAddress(&pa, g_wdh);  wdh  = (__half*)pa;
    cudaGetSymbolAddress(&pa, g_wdl);  wdl  = (__half*)pa;
    cudaGetSymbolAddress(&pa, g_wukh); wukh = (__half*)pa;
    cudaGetSymbolAddress(&pa, g_wukl); wukl = (__half*)pa;
    cudaGetSymbolAddress(&pa, g_wuvh); wuvh = (__half*)pa;
    cudaGetSymbolAddress(&pa, g_wuvl); wuvl = (__half*)pa;
    cudaGetSymbolAddress(&pa, g_wqh);  wqh  = (__half*)pa;
    cudaGetSymbolAddress(&pa, g_wql);  wql  = (__half*)pa;
    cudaGetSymbolAddress(&pa, g_woh);  woh  = (__half*)pa;
    cudaGetSymbolAddress(&pa, g_wol);  wol  = (__half*)pa;

    static bool attr_set = false;
    if (!attr_set) {
        cudaFuncSetAttribute(hgemm, cudaFuncAttributeMaxDynamicSharedMemorySize, SMEM_HGEMM);
        cudaFuncSetAttribute(flash_kernel, cudaFuncAttributeMaxDynamicSharedMemorySize, SMEM_FLASH);
        attr_set = true;
    }

    const float inv_sqrt_dh = 0.08838834764831845f;
    dim3 blk(256);

    // 0) prep: x split + all weight transposes
    prep_kernel<<<dim3(64, 64, 6), dim3(32, 8)>>>(x, W_down, W_uk, W_uv, W_q, W_o);

    // 1) q = (x @ W_q + b_q)/sqrt(DH) -> split Q
    hgemm<<<dim3(DM/128, MTOT/128), blk, SMEM_HGEMM>>>(
        xhi, xlo, wqh, wql, nullptr, qhi, qlo, nullptr, nullptr, b_q, DM, DM, DM, DM, inv_sqrt_dh);

    // 2) latents = x @ W_down + b_down -> split lat
    hgemm<<<dim3(DL/128, MTOT/128), blk, SMEM_HGEMM>>>(
        xhi, xlo, wdh, wdl, nullptr, lathi, latlo, nullptr, nullptr, b_down, DM, DM, DM, DL, 1.0f);

    // 3) keys = lat @ W_uk + b_uk -> split K
    hgemm<<<dim3(DM/128, MTOT/128), blk, SMEM_HGEMM>>>(
        lathi, latlo, wukh, wukl, nullptr, khi, klo, nullptr, nullptr, b_uk, DL, DL, DL, DM, 1.0f);

    // 4) values = lat @ W_uv + b_uv -> V^T split (fused transpose)
    hgemm<<<dim3(DM/128, MTOT/128), blk, SMEM_HGEMM>>>(
        lathi, latlo, wuvh, wuvl, nullptr, nullptr, nullptr, vthi, vtlo, b_uv, DL, DL, DL, DM, 1.0f);

    // 5) flash attention -> split ctx   (launch #5: profiled by ncu -s 5)
    flash_kernel<<<dim3(SQ/128, BB*NH), blk, SMEM_FLASH>>>(
        qhi, qlo, khi, klo, vthi, vtlo, ctxhi, ctxlo);

    // 6) out = ctx @ W_o + b_o
    hgemm<<<dim3(DM/128, MTOT/128), blk, SMEM_HGEMM>>>(
        ctxhi, ctxlo, woh, wol, out, nullptr, nullptr, nullptr, nullptr, b_o, DM, DM, DM, DM, 1.0f);
}

// round 9
// speedup vs baseline: 1.0606x; 1.0606x over previous
#include <cuda_runtime.h>
#include <cuda_fp16.h>
#include <math.h>
#include <stdint.h>

#define SQ   2048
#define DM   2048
#define DH   128
#define NH   16
#define DL   512
#define BB   4
#define MTOT (BB*SQ)

// ---------------- scratch ------------------------------------------------------
__device__ __half g_xhi[(size_t)MTOT * DM],  g_xlo[(size_t)MTOT * DM];
__device__ __half g_lathi[(size_t)MTOT * DL], g_latlo[(size_t)MTOT * DL];
__device__ __half g_khi[(size_t)MTOT * DM],  g_klo[(size_t)MTOT * DM];
__device__ __half g_qhi[(size_t)MTOT * DM],  g_qlo[(size_t)MTOT * DM];
__device__ __half g_ctxhi[(size_t)MTOT * DM], g_ctxlo[(size_t)MTOT * DM];
__device__ __half g_vthi[(size_t)BB * NH * DH * SQ], g_vtlo[(size_t)BB * NH * DH * SQ];
__device__ __half g_wdh[(size_t)DM * DL], g_wdl[(size_t)DM * DL];
__device__ __half g_wukh[(size_t)DL * DM], g_wukl[(size_t)DL * DM];
__device__ __half g_wuvh[(size_t)DL * DM], g_wuvl[(size_t)DL * DM];
__device__ __half g_wqh[(size_t)DM * DM],  g_wql[(size_t)DM * DM];
__device__ __half g_woh[(size_t)DM * DM],  g_wol[(size_t)DM * DM];

// ---------------- helpers ------------------------------------------------------
__device__ __forceinline__ uint32_t smem_u32(const void* p) {
    uint32_t a;
    asm("{ .reg .u64 t; cvta.to.shared.u64 t, %1; cvt.u32.u64 %0, t; }" : "=r"(a) : "l"(p));
    return a;
}
__device__ __forceinline__ void cp_async16(uint32_t dst, const void* src) {
    asm volatile("cp.async.cg.shared.global [%0], [%1], 16;" :: "r"(dst), "l"(src) : "memory");
}
#define CP_COMMIT() asm volatile("cp.async.commit_group;" ::: "memory")
#define CP_WAIT1()  asm volatile("cp.async.wait_group 1;" ::: "memory")

__device__ __forceinline__ void split_h2(float2 f, uint32_t& hi, uint32_t& lo) {
    __half2 h = __float22half2_rn(f);
    float2 back = __half22float2(h);
    __half2 l = __float22half2_rn(make_float2(f.x - back.x, f.y - back.y));
    hi = *(uint32_t*)&h;
    lo = *(uint32_t*)&l;
}
__device__ __forceinline__ uint32_t pack_h2(float a, float b) {
    __half2 h = __float22half2_rn(make_float2(a, b));
    return *(uint32_t*)&h;
}
__device__ __forceinline__ void mma_f16(float* c, const uint32_t* a, const uint32_t* b) {
    asm volatile(
        "mma.sync.aligned.m16n8k16.row.col.f32.f16.f16.f32 "
        "{%0,%1,%2,%3}, {%4,%5,%6,%7}, {%8,%9}, {%0,%1,%2,%3};"
        : "+f"(c[0]), "+f"(c[1]), "+f"(c[2]), "+f"(c[3])
        : "r"(a[0]), "r"(a[1]), "r"(a[2]), "r"(a[3]), "r"(b[0]), "r"(b[1]));
}
__device__ __forceinline__ int inv_pair(int p) { return ((p & 3) << 1) | (p >> 2); }

// ---------------- prep: x split + 5 weight transpose/splits --------------------
__global__ void prep_kernel(const float* __restrict__ x,
                            const float* __restrict__ Wd, const float* __restrict__ Wuk,
                            const float* __restrict__ Wuv, const float* __restrict__ Wq,
                            const float* __restrict__ Wo)
{
    const int z = blockIdx.z;
    if (z == 0) {
        const int tid = threadIdx.y * 32 + threadIdx.x;
        long long base = ((long long)blockIdx.y * 64 + blockIdx.x) * 256 + tid;
        const long long tot = (long long)MTOT * DM / 2;
        for (long long i2 = base; i2 < tot; i2 += (long long)4096 * 256) {
            int d2 = (int)(i2 & (DM / 2 - 1));
            long long row = i2 >> 10;
            int d2p = (d2 & ~7) | inv_pair(d2 & 7);
            float2 v = ((const float2*)x)[i2];
            uint32_t h, l;
            split_h2(v, h, l);
            ((uint32_t*)g_xhi)[row * (DM / 2) + d2p] = h;
            ((uint32_t*)g_xlo)[row * (DM / 2) + d2p] = l;
        }
        return;
    }
    const float* in; __half *hi, *lo; int Cc, R;
    if      (z == 1) { in = Wd;  hi = g_wdh;  lo = g_wdl;  Cc = DL; R = DM; }
    else if (z == 2) { in = Wuk; hi = g_wukh; lo = g_wukl; Cc = DM; R = DL; }
    else if (z == 3) { in = Wuv; hi = g_wuvh; lo = g_wuvl; Cc = DM; R = DL; }
    else if (z == 4) { in = Wq;  hi = g_wqh;  lo = g_wql;  Cc = DM; R = DM; }
    else             { in = Wo;  hi = g_woh;  lo = g_wol;  Cc = DM; R = DM; }
    const int c0 = blockIdx.x * 32, r0 = blockIdx.y * 32;
    if (c0 >= Cc || r0 >= R) return;

    __shared__ float t[32][33];
#pragma unroll
    for (int i = threadIdx.y; i < 32; i += 8)
        t[i][threadIdx.x] = in[(long long)(r0 + i) * Cc + c0 + threadIdx.x];
    __syncthreads();
    const int e = r0 + threadIdx.x;
    const int p = e >> 1, bo = e & 1;
    const int pe = (((p & ~7) | inv_pair(p & 7)) << 1) | bo;
#pragma unroll
    for (int i = threadIdx.y; i < 32; i += 8) {
        float v = t[threadIdx.x][i];
        __half h = __float2half_rn(v);
        __half l = __float2half_rn(v - __half2float(h));
        hi[(long long)(c0 + i) * R + pe] = h;
        lo[(long long)(c0 + i) * R + pe] = l;
    }
}

// ---------------- pre-split fp16 hi/lo GEMM ------------------------------------
#define BK 32
#define AROW 80
#define ARR (128 * AROW)
#define HSTAGE (4 * ARR)
#define SMEM_HGEMM (2 * HSTAGE)         // 81920

__global__ __launch_bounds__(256, 2)
void hgemm(const __half* __restrict__ Ah, const __half* __restrict__ Al,
           const __half* __restrict__ Bh, const __half* __restrict__ Bl,
           float* __restrict__ Cf, __half* __restrict__ Chi, __half* __restrict__ Clo,
           __half* __restrict__ VtHi, __half* __restrict__ VtLo,
           const float* __restrict__ bias,
           int K, int lda, int ldb, int ldc, float post)
{
    extern __shared__ char sm[];
    const uint32_t smb = smem_u32(sm);
    const int tid = threadIdx.x, wid = tid >> 5, lane = tid & 31;
    const int qr = lane >> 2, qc = lane & 3;
    const int warpM = (wid & 1) * 64, warpN = (wid >> 1) * 32;
    const int m0 = blockIdx.y * 128, n0 = blockIdx.x * 128;

    const __half* A0 = Ah + (long long)m0 * lda;
    const __half* A1 = Al + (long long)m0 * lda;
    const __half* B0 = Bh + (long long)n0 * ldb;
    const __half* B1 = Bl + (long long)n0 * ldb;

    float acc[4][4][4];
#pragma unroll
    for (int mi = 0; mi < 4; mi++)
#pragma unroll
        for (int ni = 0; ni < 4; ni++)
#pragma unroll
            for (int t = 0; t < 4; t++) acc[mi][ni][t] = 0.0f;

    auto load_stage = [&](int t, int s) {
        const int k0 = t * BK;
        uint32_t base = smb + s * HSTAGE;
#pragma unroll
        for (int j = 0; j < 2; j++) {
            int g = tid + j * 256;
            int r = g >> 2, c = g & 3;
            uint32_t off = (uint32_t)(r * AROW + c * 16);
            cp_async16(base + off,           A0 + (long long)r * lda + k0 + c * 8);
            cp_async16(base + ARR + off,     A1 + (long long)r * lda + k0 + c * 8);
            cp_async16(base + 2 * ARR + off, B0 + (long long)r * ldb + k0 + c * 8);
            cp_async16(base + 3 * ARR + off, B1 + (long long)r * ldb + k0 + c * 8);
        }
    };

    const int nk = K / BK;
    load_stage(0, 0); CP_COMMIT();
    load_stage(1, 1); CP_COMMIT();

    for (int i = 0; i < nk; i++) {
        CP_WAIT1();
        __syncthreads();
        const char* s = sm + (i & 1) * HSTAGE;
#pragma unroll
        for (int kk = 0; kk < 2; kk++) {
            uint32_t aH[4][4], aL[4][4], bH[4][2], bL[4][2];
#pragma unroll
            for (int mi = 0; mi < 4; mi++) {
                int row = warpM + mi * 16 + qr;
                uint2 v0 = *(const uint2*)(s + row * AROW + kk * 32 + qc * 8);
                uint2 v1 = *(const uint2*)(s + (row + 8) * AROW + kk * 32 + qc * 8);
                aH[mi][0] = v0.x; aH[mi][2] = v0.y; aH[mi][1] = v1.x; aH[mi][3] = v1.y;
                uint2 w0 = *(const uint2*)(s + ARR + row * AROW + kk * 32 + qc * 8);
                uint2 w1 = *(const uint2*)(s + ARR + (row + 8) * AROW + kk * 32 + qc * 8);
                aL[mi][0] = w0.x; aL[mi][2] = w0.y; aL[mi][1] = w1.x; aL[mi][3] = w1.y;
            }
#pragma unroll
            for (int ni = 0; ni < 4; ni++) {
                int col = warpN + ni * 8 + qr;
                uint2 v = *(const uint2*)(s + 2 * ARR + col * AROW + kk * 32 + qc * 8);
                bH[ni][0] = v.x; bH[ni][1] = v.y;
                uint2 w = *(const uint2*)(s + 3 * ARR + col * AROW + kk * 32 + qc * 8);
                bL[ni][0] = w.x; bL[ni][1] = w.y;
            }
#pragma unroll
            for (int mi = 0; mi < 4; mi++)
#pragma unroll
                for (int ni = 0; ni < 4; ni++) {
                    mma_f16(acc[mi][ni], aL[mi], bH[ni]);
                    mma_f16(acc[mi][ni], aH[mi], bL[ni]);
                    mma_f16(acc[mi][ni], aH[mi], bH[ni]);
                }
        }
        __syncthreads();
        if (i + 2 < nk) load_stage(i + 2, i & 1);
        CP_COMMIT();
    }

    if (VtHi) {
        __syncthreads();
        float* tile = (float*)sm;   // [128][132]
#pragma unroll
        for (int mi = 0; mi < 4; mi++)
#pragma unroll
            for (int ni = 0; ni < 4; ni++) {
                int rl = warpM + mi * 16 + qr;
                int cl = warpN + ni * 8 + qc * 2;
                float2 bv = *(const float2*)(bias + n0 + cl);
                tile[rl * 132 + cl]       = acc[mi][ni][0] + bv.x;
                tile[rl * 132 + cl + 1]   = acc[mi][ni][1] + bv.y;
                tile[(rl + 8) * 132 + cl]     = acc[mi][ni][2] + bv.x;
                tile[(rl + 8) * 132 + cl + 1] = acc[mi][ni][3] + bv.y;
            }
        __syncthreads();
        const int h = n0 >> 7;
        const int bb = m0 >> 11;
        const int s0g = m0 & (SQ - 1);
        const int dl = tid >> 1, sh = (tid & 1) * 64;
        long long base = ((long long)(bb * NH + h) * DH + dl) * SQ + s0g + sh;
#pragma unroll
        for (int pp = 0; pp < 32; pp++) {
            int e = 2 * pp;
            int g = e >> 4, q = pp & 7;
            int off = g * 16 + inv_pair(q) * 2;
            float v0 = tile[(sh + e) * 132 + dl];
            float v1 = tile[(sh + e + 1) * 132 + dl];
            uint32_t hh, ll;
            split_h2(make_float2(v0, v1), hh, ll);
            *(uint32_t*)(VtHi + base + off) = hh;
            *(uint32_t*)(VtLo + base + off) = ll;
        }
        return;
    }

#pragma unroll
    for (int mi = 0; mi < 4; mi++) {
#pragma unroll
        for (int ni = 0; ni < 4; ni++) {
            int row = m0 + warpM + mi * 16 + qr;
            int colb = n0 + warpN + ni * 8;
            float2 bv = make_float2(0.f, 0.f);
            if (bias) bv = *(const float2*)(bias + colb + qc * 2);
            float2 v0 = make_float2((acc[mi][ni][0] + bv.x) * post, (acc[mi][ni][1] + bv.y) * post);
            float2 v1 = make_float2((acc[mi][ni][2] + bv.x) * post, (acc[mi][ni][3] + bv.y) * post);
            if (Cf) {
                *(float2*)(Cf + (long long)row * ldc + colb + qc * 2) = v0;
                *(float2*)(Cf + (long long)(row + 8) * ldc + colb + qc * 2) = v1;
            }
            if (Chi) {
                int p = (colb >> 1) + qc;
                int pp = (p & ~7) | inv_pair(p & 7);
                uint32_t h, l;
                split_h2(v0, h, l);
                ((uint32_t*)Chi)[(long long)row * (ldc >> 1) + pp] = h;
                ((uint32_t*)Clo)[(long long)row * (ldc >> 1) + pp] = l;
                split_h2(v1, h, l);
                ((uint32_t*)Chi)[(long long)(row + 8) * (ldc >> 1) + pp] = h;
                ((uint32_t*)Clo)[(long long)(row + 8) * (ldc >> 1) + pp] = l;
            }
        }
    }
}

// ---------------- fused flash attention ----------------------------------------
// Q (hi/lo) resident in smem; K hi/lo + single-fp16 V double-buffered.
#define CHUNK 64
#define QROWB 272
#define KROWB 272
#define VROWB 144
#define SM_QH 0
#define SM_QL (128 * QROWB)              // 34816
#define KV0   (2 * 128 * QROWB)          // 69632
#define KVSTG 53248                      // KH 17408 + KL 17408 + V 18432
#define FKH(s) (KV0 + (s) * KVSTG)
#define FKL(s) (KV0 + (s) * KVSTG + 17408)
#define FV(s)  (KV0 + (s) * KVSTG + 34816)
#define SMEM_FLASH (KV0 + 2 * KVSTG)     // 176128

__global__ __launch_bounds__(256)
void flash_kernel(const __half* __restrict__ Qhi, const __half* __restrict__ Qlo,
                  const __half* __restrict__ Khi, const __half* __restrict__ Klo,
                  const __half* __restrict__ Vhi,
                  __half* __restrict__ Chi, __half* __restrict__ Clo)
{
    extern __shared__ char smc[];
    const uint32_t smb = smem_u32(smc);
    const int tid = threadIdx.x, wid = tid >> 5, lane = tid & 31;
    const int qr = lane >> 2, qc = lane & 3;
    const int bh = blockIdx.y, b = bh >> 4, h = bh & 15;
    const int q0 = blockIdx.x * 128;

    const long long qbase = (long long)(b * SQ + q0);

    // ---- stage Q hi/lo into smem (once) ----
    {
        const __half* qh_g = Qhi + qbase * DM + h * DH;
        const __half* ql_g = Qlo + qbase * DM + h * DH;
        for (int g = tid; g < 2048; g += 256) {
            int r = g >> 4, c = g & 15;
            cp_async16(smb + SM_QH + r * QROWB + c * 16, qh_g + (long long)r * DM + c * 8);
            cp_async16(smb + SM_QL + r * QROWB + c * 16, ql_g + (long long)r * DM + c * 8);
        }
    }

    float accO[16][4];
#pragma unroll
    for (int t = 0; t < 16; t++)
#pragma unroll
        for (int c = 0; c < 4; c++) accO[t][c] = 0.0f;
    float mr0 = -INFINITY, mr1 = -INFINITY, lr0 = 0.0f, lr1 = 0.0f;

    const __half* kh_g = Khi + (long long)(b * SQ) * DM + h * DH;
    const __half* kl_g = Klo + (long long)(b * SQ) * DM + h * DH;
    const __half* vh_g = Vhi + (long long)bh * DH * SQ;

    auto loadKV = [&](int j, int s) {
        int s0 = j * CHUNK;
        for (int g = tid; g < 1024; g += 256) {
            int r = g >> 4, c = g & 15;
            cp_async16(smb + FKH(s) + r * KROWB + c * 16, kh_g + (long long)(s0 + r) * DM + c * 8);
            cp_async16(smb + FKL(s) + r * KROWB + c * 16, kl_g + (long long)(s0 + r) * DM + c * 8);
        }
        for (int g = tid; g < 1024; g += 256) {
            int r = g >> 3, c = g & 7;
            cp_async16(smb + FV(s) + r * VROWB + c * 16, vh_g + (long long)r * SQ + s0 + c * 8);
        }
    };

    loadKV(0, 0);       // group 0 = Q + KV0
    CP_COMMIT();

    const char* qhp = smc + SM_QH + (wid * 16 + qr) * QROWB;
    const char* qlp = smc + SM_QL + (wid * 16 + qr) * QROWB;

    const int NCH = SQ / CHUNK;
    for (int j = 0; j < NCH; j++) {
        if (j + 1 < NCH) loadKV(j + 1, (j + 1) & 1);
        CP_COMMIT();
        CP_WAIT1();                // Q + KV(j) complete; KV(j+1) in flight
        __syncthreads();
        const int st = j & 1;

        // ---- S = Q @ K^T (3-term) ----
        float accS[8][4];
#pragma unroll
        for (int t = 0; t < 8; t++)
#pragma unroll
            for (int c = 0; c < 4; c++) accS[t][c] = 0.0f;
#pragma unroll
        for (int kk = 0; kk < 8; kk++) {
            uint32_t aH[4], aL[4];
            {
                uint2 v0 = *(const uint2*)(qhp + kk * 32 + qc * 8);
                uint2 v1 = *(const uint2*)(qhp + 8 * QROWB + kk * 32 + qc * 8);
                aH[0] = v0.x; aH[2] = v0.y; aH[1] = v1.x; aH[3] = v1.y;
                uint2 w0 = *(const uint2*)(qlp + kk * 32 + qc * 8);
                uint2 w1 = *(const uint2*)(qlp + 8 * QROWB + kk * 32 + qc * 8);
                aL[0] = w0.x; aL[2] = w0.y; aL[1] = w1.x; aL[3] = w1.y;
            }
#pragma unroll
            for (int t = 0; t < 8; t++) {
                uint2 bhv = *(const uint2*)(smc + FKH(st) + (8 * t + qr) * KROWB + kk * 32 + qc * 8);
                uint2 blv = *(const uint2*)(smc + FKL(st) + (8 * t + qr) * KROWB + kk * 32 + qc * 8);
                uint32_t bH[2] = {bhv.x, bhv.y}, bL[2] = {blv.x, blv.y};
                mma_f16(accS[t], aL, bH);
                mma_f16(accS[t], aH, bL);
                mma_f16(accS[t], aH, bH);
            }
        }

        // ---- online softmax (rescale only when max moves) ----
        float mx0 = -INFINITY, mx1 = -INFINITY;
#pragma unroll
        for (int t = 0; t < 8; t++) {
            mx0 = fmaxf(mx0, fmaxf(accS[t][0], accS[t][1]));
            mx1 = fmaxf(mx1, fmaxf(accS[t][2], accS[t][3]));
        }
        mx0 = fmaxf(mx0, __shfl_xor_sync(0xFFFFFFFFu, mx0, 1));
        mx0 = fmaxf(mx0, __shfl_xor_sync(0xFFFFFFFFu, mx0, 2));
        mx1 = fmaxf(mx1, __shfl_xor_sync(0xFFFFFFFFu, mx1, 1));
        mx1 = fmaxf(mx1, __shfl_xor_sync(0xFFFFFFFFu, mx1, 2));
        if (mx0 > mr0 || mx1 > mr1) {
            float mn0 = fmaxf(mr0, mx0), mn1 = fmaxf(mr1, mx1);
            float al0 = __expf(mr0 - mn0), al1 = __expf(mr1 - mn1);
            mr0 = mn0; mr1 = mn1;
            lr0 *= al0; lr1 *= al1;
#pragma unroll
            for (int t = 0; t < 16; t++) {
                accO[t][0] *= al0; accO[t][1] *= al0;
                accO[t][2] *= al1; accO[t][3] *= al1;
            }
        }
        uint32_t ph[8][2];
#pragma unroll
        for (int t = 0; t < 8; t++) {
            float p0 = __expf(accS[t][0] - mr0);
            float p1 = __expf(accS[t][1] - mr0);
            float p2 = __expf(accS[t][2] - mr1);
            float p3 = __expf(accS[t][3] - mr1);
            lr0 += p0 + p1;
            lr1 += p2 + p3;
            ph[t][0] = pack_h2(p0, p1);
            ph[t][1] = pack_h2(p2, p3);
        }

        // ---- O += P @ V (single fp16 V) ----
#pragma unroll
        for (int kk2 = 0; kk2 < 4; kk2++) {
            uint32_t aH[4] = {ph[2 * kk2][0], ph[2 * kk2][1], ph[2 * kk2 + 1][0], ph[2 * kk2 + 1][1]};
#pragma unroll
            for (int t = 0; t < 16; t++) {
                uint2 vh2 = *(const uint2*)(smc + FV(st) + (8 * t + qr) * VROWB + kk2 * 32 + qc * 8);
                uint32_t bV[2] = {vh2.x, vh2.y};
                mma_f16(accO[t], aH, bV);
            }
        }
        __syncthreads();
    }

    // ---- epilogue: normalize, split, store ----
    lr0 += __shfl_xor_sync(0xFFFFFFFFu, lr0, 1);
    lr0 += __shfl_xor_sync(0xFFFFFFFFu, lr0, 2);
    lr1 += __shfl_xor_sync(0xFFFFFFFFu, lr1, 1);
    lr1 += __shfl_xor_sync(0xFFFFFFFFu, lr1, 2);
    const float i0 = 1.0f / lr0, i1 = 1.0f / lr1;
    const long long rowA = qbase + wid * 16 + qr;
#pragma unroll
    for (int t = 0; t < 16; t++) {
        int p = 64 * h + 4 * t + qc;
        int pp = (p & ~7) | inv_pair(p & 7);
        uint32_t hh, ll;
        split_h2(make_float2(accO[t][0] * i0, accO[t][1] * i0), hh, ll);
        ((uint32_t*)Chi)[rowA * (DM / 2) + pp] = hh;
        ((uint32_t*)Clo)[rowA * (DM / 2) + pp] = ll;
        split_h2(make_float2(accO[t][2] * i1, accO[t][3] * i1), hh, ll);
        ((uint32_t*)Chi)[(rowA + 8) * (DM / 2) + pp] = hh;
        ((uint32_t*)Clo)[(rowA + 8) * (DM / 2) + pp] = ll;
    }
}

// ---------------- launch -------------------------------------------------------
extern "C" void kernel_launch(void* const* d_in, const int* in_sizes, int n_in,
                              void* d_out, int out_size)
{
    const float* x      = (const float*)d_in[0];
    const float* W_down = (const float*)d_in[1];
    const float* b_down = (const float*)d_in[2];
    const float* W_uk   = (const float*)d_in[3];
    const float* b_uk   = (const float*)d_in[4];
    const float* W_uv   = (const float*)d_in[5];
    const float* b_uv   = (const float*)d_in[6];
    const float* W_q    = (const float*)d_in[7];
    const float* b_q    = (const float*)d_in[8];
    const float* W_o    = (const float*)d_in[9];
    const float* b_o    = (const float*)d_in[10];
    float* out = (float*)d_out;

    void *pa;
    cudaGetSymbolAddress(&pa, g_xhi);   __half* xhi = (__half*)pa;
    cudaGetSymbolAddress(&pa, g_xlo);   __half* xlo = (__half*)pa;
    cudaGetSymbolAddress(&pa, g_lathi); __half* lathi = (__half*)pa;
    cudaGetSymbolAddress(&pa, g_latlo); __half* latlo = (__half*)pa;
    cudaGetSymbolAddress(&pa, g_khi);   __half* khi = (__half*)pa;
    cudaGetSymbolAddress(&pa, g_klo);   __half* klo = (__half*)pa;
    cudaGetSymbolAddress(&pa, g_qhi);   __half* qhi = (__half*)pa;
    cudaGetSymbolAddress(&pa, g_qlo);   __half* qlo = (__half*)pa;
    cudaGetSymbolAddress(&pa, g_ctxhi); __half* ctxhi = (__half*)pa;
    cudaGetSymbolAddress(&pa, g_ctxlo); __half* ctxlo = (__half*)pa;
    cudaGetSymbolAddress(&pa, g_vthi);  __half* vthi = (__half*)pa;
    cudaGetSymbolAddress(&pa, g_vtlo);  __half* vtlo = (__half*)pa;
    __half *wdh, *wdl, *wukh, *wukl, *wuvh, *wuvl, *wqh, *wql, *woh, *wol;
    cudaGetSymbolAddress(&pa, g_wdh);  wdh  = (__half*)pa;
    cudaGetSymbolAddress(&pa, g_wdl);  wdl  = (__half*)pa;
    cudaGetSymbolAddress(&pa, g_wukh); wukh = (__half*)pa;
    cudaGetSymbolAddress(&pa, g_wukl); wukl = (__half*)pa;
    cudaGetSymbolAddress(&pa, g_wuvh); wuvh = (__half*)pa;
    cudaGetSymbolAddress(&pa, g_wuvl); wuvl = (__half*)pa;
    cudaGetSymbolAddress(&pa, g_wqh);  wqh  = (__half*)pa;
    cudaGetSymbolAddress(&pa, g_wql);  wql  = (__half*)pa;
    cudaGetSymbolAddress(&pa, g_woh);  woh  = (__half*)pa;
    cudaGetSymbolAddress(&pa, g_wol);  wol  = (__half*)pa;

    static bool attr_set = false;
    if (!attr_set) {
        cudaFuncSetAttribute(hgemm, cudaFuncAttributeMaxDynamicSharedMemorySize, SMEM_HGEMM);
        cudaFuncSetAttribute(flash_kernel, cudaFuncAttributeMaxDynamicSharedMemorySize, SMEM_FLASH);
        attr_set = true;
    }

    const float inv_sqrt_dh = 0.08838834764831845f;
    dim3 blk(256);

    // 0) prep
    prep_kernel<<<dim3(64, 64, 6), dim3(32, 8)>>>(x, W_down, W_uk, W_uv, W_q, W_o);

    // 1) q = (x @ W_q + b_q)/sqrt(DH) -> split Q
    hgemm<<<dim3(DM/128, MTOT/128), blk, SMEM_HGEMM>>>(
        xhi, xlo, wqh, wql, nullptr, qhi, qlo, nullptr, nullptr, b_q, DM, DM, DM, DM, inv_sqrt_dh);

    // 2) latents -> split lat
    hgemm<<<dim3(DL/128, MTOT/128), blk, SMEM_HGEMM>>>(
        xhi, xlo, wdh, wdl, nullptr, lathi, latlo, nullptr, nullptr, b_down, DM, DM, DM, DL, 1.0f);

    // 3) keys -> split K
    hgemm<<<dim3(DM/128, MTOT/128), blk, SMEM_HGEMM>>>(
        lathi, latlo, wukh, wukl, nullptr, khi, klo, nullptr, nullptr, b_uk, DL, DL, DL, DM, 1.0f);

    // 4) values -> V^T split (fused transpose)
    hgemm<<<dim3(DM/128, MTOT/128), blk, SMEM_HGEMM>>>(
        lathi, latlo, wuvh, wuvl, nullptr, nullptr, nullptr, vthi, vtlo, b_uv, DL, DL, DL, DM, 1.0f);

    // 5) flash attention -> split ctx
    flash_kernel<<<dim3(SQ/128, BB*NH), blk, SMEM_FLASH>>>(
        qhi, qlo, khi, klo, vthi, ctxhi, ctxlo);

    // 6) out = ctx @ W_o + b_o
    hgemm<<<dim3(DM/128, MTOT/128), blk, SMEM_HGEMM>>>(
        ctxhi, ctxlo, woh, wol, out, nullptr, nullptr, nullptr, nullptr, b_o, DM, DM, DM, DM, 1.0f);
}